// round 8
// baseline (speedup 1.0000x reference)
#include <cuda_runtime.h>
#include <math.h>

#define Bn 128
#define Cn 48
#define Hn 64
#define Wn 64
#define Pn 32
#define OUT_ELEMS (Bn*Cn*Hn*Wn)

// Scratch (no allocations allowed)
__device__ unsigned long long g_M2[Cn*Cn];   // M duplicated (m,m) as f32x2
__device__ float4 g_Spart[1024];             // partials: idx = (b*2+g)*4 + kq
__device__ float  g_A[Bn*2*4];               // attn coeffs per (b,g)

#define FMA2(acc, mm, vv) asm("fma.rn.f32x2 %0, %1, %2, %0;" : "+l"(acc) : "l"(mm), "l"(vv))
#define PACK2(dst, lo, hi) asm("mov.b64 %0, {%1,%2};" : "=l"(dst) : "f"(lo), "f"(hi))
#define UNPACK2(lo, hi, src) asm("mov.b64 {%0,%1}, %2;" : "=f"(lo), "=f"(hi) : "l"(src))

// ---------------------------------------------------------------------------
// Kernel A: prep. 9 blocks x 256 threads, smem-staged W, 1 output/thread.
// ---------------------------------------------------------------------------
__global__ __launch_bounds__(256) void prep_kernel(
        const float* __restrict__ Wq1, const float* __restrict__ Wq2,
        const float* __restrict__ Wq3, const float* __restrict__ Wk1,
        const float* __restrict__ Wk2, const float* __restrict__ Wk3) {
    __shared__ float sW[6][Cn*Cn];   // 55296 B

    const int tid = threadIdx.x;
    const float* Ws[6] = {Wq1, Wk1, Wq2, Wk2, Wq3, Wk3};
    #pragma unroll
    for (int m = 0; m < 6; ++m)
        for (int i = tid; i < Cn*Cn; i += 256) sW[m][i] = Ws[m][i];
    __syncthreads();

    int w = blockIdx.x * 256 + tid;          // 0..2303
    int c = w / Cn, c2 = w % Cn;
    float s = 0.f;
    #pragma unroll
    for (int o = 0; o < Cn; ++o) {
        s += sW[0][o*Cn+c]*sW[1][o*Cn+c2]
           + sW[2][o*Cn+c]*sW[3][o*Cn+c2]
           + sW[4][o*Cn+c]*sW[5][o*Cn+c2];
    }
    s *= (1.0f / sqrtf((float)(Cn*Pn*Pn)));
    ((float2*)g_M2)[w] = make_float2(s, s);
}

// ---------------------------------------------------------------------------
// Kernel B: scores. Grid 1024: bid -> (b, g, k-quarter kq). Block 256 = 8 warps.
// c2 processed in pairs: one LDS.128 broadcast per M row pair -> halves the
// broadcast crossbar phases vs R6.
// ---------------------------------------------------------------------------
__global__ __launch_bounds__(256, 3) void score_kernel(const float* __restrict__ x) {
    __shared__ unsigned long long sV[Cn*128];   // 49152 B  [c][k]
    __shared__ unsigned long long sM2[Cn*Cn];   // 18432 B
    __shared__ float4 sred[8];

    const int bid = blockIdx.x;
    const int kq = bid & 3;            // k-quarter (8 y-rows)
    const int g  = (bid >> 2) & 1;     // column-parity group
    const int b  = bid >> 3;
    const int tid = threadIdx.x;

    for (int i = tid; i < Cn*Cn; i += 256) sM2[i] = g_M2[i];

    const float2* xb2 = (const float2*)(x + (size_t)b * Cn * Hn * Wn);

    for (int idx = tid; idx < Cn*128; idx += 256) {
        int c2 = idx >> 7;
        int k  = idx & 127;
        int yy = k >> 4;
        int xx = k & 15;
        int yt = kq*8 + yy;
        float2 a  = xb2[((size_t)c2*Hn + yt)*32      + g*16 + xx];
        float2 bb = xb2[((size_t)c2*Hn + yt + 32)*32 + g*16 + xx];
        unsigned long long pk;
        if (g == 0) PACK2(pk, a.x, bb.x);
        else        PACK2(pk, a.y, bb.y);
        sV[idx] = pk;
    }
    __syncthreads();

    const int ci = tid >> 5;           // warp id: M-row group
    const int kl = tid & 31;           // k lane

    unsigned long long acc[24];
    #pragma unroll
    for (int i = 0; i < 24; ++i) acc[i] = 0ULL;

    #pragma unroll
    for (int c2 = 0; c2 < Cn; c2 += 2) {
        // one 16B broadcast per row covers M[r][c2] and M[r][c2+1]
        ulonglong2 mm[6];
        #pragma unroll
        for (int r = 0; r < 6; ++r)
            mm[r] = *(const ulonglong2*)&sM2[(ci*6 + r)*Cn + c2];

        {
            unsigned long long v0 = sV[c2*128 + kl];
            unsigned long long v1 = sV[c2*128 + kl + 32];
            unsigned long long v2 = sV[c2*128 + kl + 64];
            unsigned long long v3 = sV[c2*128 + kl + 96];
            #pragma unroll
            for (int r = 0; r < 6; ++r) {
                FMA2(acc[r*4    ], mm[r].x, v0);
                FMA2(acc[r*4 + 1], mm[r].x, v1);
                FMA2(acc[r*4 + 2], mm[r].x, v2);
                FMA2(acc[r*4 + 3], mm[r].x, v3);
            }
        }
        {
            unsigned long long v0 = sV[(c2+1)*128 + kl];
            unsigned long long v1 = sV[(c2+1)*128 + kl + 32];
            unsigned long long v2 = sV[(c2+1)*128 + kl + 64];
            unsigned long long v3 = sV[(c2+1)*128 + kl + 96];
            #pragma unroll
            for (int r = 0; r < 6; ++r) {
                FMA2(acc[r*4    ], mm[r].y, v0);
                FMA2(acc[r*4 + 1], mm[r].y, v1);
                FMA2(acc[r*4 + 2], mm[r].y, v2);
                FMA2(acc[r*4 + 3], mm[r].y, v3);
            }
        }
    }

    float p00 = 0.f, p01 = 0.f, p10 = 0.f, p11 = 0.f;
    #pragma unroll
    for (int r = 0; r < 6; ++r) {
        #pragma unroll
        for (int j = 0; j < 4; ++j) {
            float wt, wb, vt, vb;
            UNPACK2(wt, wb, acc[r*4 + j]);
            unsigned long long v = sV[(ci*6 + r)*128 + kl + j*32];
            UNPACK2(vt, vb, v);
            p00 = fmaf(vt, wt, p00);  p01 = fmaf(vt, wb, p01);
            p10 = fmaf(vb, wt, p10);  p11 = fmaf(vb, wb, p11);
        }
    }

    #pragma unroll
    for (int off = 16; off; off >>= 1) {
        p00 += __shfl_xor_sync(0xffffffffu, p00, off);
        p01 += __shfl_xor_sync(0xffffffffu, p01, off);
        p10 += __shfl_xor_sync(0xffffffffu, p10, off);
        p11 += __shfl_xor_sync(0xffffffffu, p11, off);
    }
    if (kl == 0) sred[ci] = make_float4(p00, p01, p10, p11);
    __syncthreads();
    if (tid == 0) {
        float4 sv = sred[0];
        #pragma unroll
        for (int w = 1; w < 8; ++w) {
            float4 t = sred[w];
            sv.x += t.x; sv.y += t.y; sv.z += t.z; sv.w += t.w;
        }
        g_Spart[(b*2+g)*4 + kq] = sv;
    }
}

// ---------------------------------------------------------------------------
// Kernel C: softmax coeffs + logdet.
// ---------------------------------------------------------------------------
__global__ void attn_kernel(const float* __restrict__ logdet_in,
                            const float* __restrict__ off1p,
                            const float* __restrict__ off2p,
                            const float* __restrict__ off3p,
                            float* __restrict__ out, int out_size) {
    int b = threadIdx.x;
    if (b >= Bn) return;
    const float off  = off1p[0];
    const float off2 = off2p[0];
    const float off3 = off3p[0];
    float ld = logdet_in[b];

    #pragma unroll
    for (int g = 0; g < 2; ++g) {
        float4 s = g_Spart[(b*2+g)*4 + 0];
        #pragma unroll
        for (int qq = 1; qq < 4; ++qq) {
            float4 t = g_Spart[(b*2+g)*4 + qq];
            s.x += t.x; s.y += t.y; s.z += t.z; s.w += t.w;
        }
        float stt = s.x + off3, stb = s.y + off3;
        float sbt = s.z + off3, sbb = s.w + off3;
        float z = off3;

        float mx   = fmaxf(fmaxf(stt, stb), z);
        float e0   = expf(stt-mx), e1 = expf(stb-mx), ez = expf(z-mx);
        float inv  = 1.f / (e0 + e1 + 2.f*ez);
        float a_tt = e0*inv + off2 + off;
        float a_tb = e1*inv + off2;

        mx  = fmaxf(fmaxf(sbt, sbb), z);
        e0  = expf(sbt-mx); e1 = expf(sbb-mx); ez = expf(z-mx);
        inv = 1.f / (e0 + e1 + 2.f*ez);
        float a_bt = e0*inv + off2;
        float a_bb = e1*inv + off2 + off;

        float det = a_tt*a_bb - a_tb*a_bt;
        ld += logf(fabsf(det)) * (float)(Pn*(Pn/2)*Cn);

        float* a = &g_A[(b*2+g)*4];
        a[0]=a_tt; a[1]=a_tb; a[2]=a_bt; a[3]=a_bb;
    }
    if (OUT_ELEMS + b < out_size) out[OUT_ELEMS + b] = ld;
}

// ---------------------------------------------------------------------------
// Kernel D: output assembly. __stwt write-through stores: no L2 allocation,
// so x (L2-resident after score) is not evicted and reads hit L2.
// ---------------------------------------------------------------------------
__global__ __launch_bounds__(256) void out_kernel(const float* __restrict__ x,
                                                  float* __restrict__ out) {
    int t  = blockIdx.x * blockDim.x + threadIdx.x;
    int x4 = t & 15;
    int y  = (t >> 4) & 31;
    int r  = t >> 9;
    int c  = r % Cn;
    int b  = r / Cn;
    int g  = x4 >> 3;

    const float* A = &g_A[(b*2+g)*4];
    float a_tt = __ldg(&A[0]), a_tb = __ldg(&A[1]);
    float a_bt = __ldg(&A[2]), a_bb = __ldg(&A[3]);

    size_t base = (((size_t)b*Cn + c)*Hn + y)*Wn + x4*4;
    float4 xt = *(const float4*)(x + base);
    float4 xb = *(const float4*)(x + base + 32*Wn);
    float4 ot, ob;
    if (g == 0) {  // pass-through at even lane (x,z)
        ot.x = xt.x;                    ob.x = xb.x;
        ot.y = a_tt*xt.y + a_tb*xb.y;   ob.y = a_bt*xt.y + a_bb*xb.y;
        ot.z = xt.z;                    ob.z = xb.z;
        ot.w = a_tt*xt.w + a_tb*xb.w;   ob.w = a_bt*xt.w + a_bb*xb.w;
    } else {       // pass-through at odd lane (y,w)
        ot.x = a_tt*xt.x + a_tb*xb.x;   ob.x = a_bt*xt.x + a_bb*xb.x;
        ot.y = xt.y;                    ob.y = xb.y;
        ot.z = a_tt*xt.z + a_tb*xb.z;   ob.z = a_bt*xt.z + a_bb*xb.z;
        ot.w = xt.w;                    ob.w = xb.w;
    }
    __stwt((float4*)(out + base), ot);
    __stwt((float4*)(out + base + 32*Wn), ob);
}

// ---------------------------------------------------------------------------
extern "C" void kernel_launch(void* const* d_in, const int* in_sizes, int n_in,
                              void* d_out, int out_size) {
    const float* x      = (const float*)d_in[0];
    const float* logdet = (const float*)d_in[1];
    const float* Wq1    = (const float*)d_in[2];
    const float* Wq2    = (const float*)d_in[3];
    const float* Wq3    = (const float*)d_in[4];
    const float* Wk1    = (const float*)d_in[5];
    const float* Wk2    = (const float*)d_in[6];
    const float* Wk3    = (const float*)d_in[7];
    const float* off1   = (const float*)d_in[8];
    const float* off2   = (const float*)d_in[9];
    const float* off3   = (const float*)d_in[10];
    float* out = (float*)d_out;

    prep_kernel<<<9, 256>>>(Wq1, Wq2, Wq3, Wk1, Wk2, Wk3);
    score_kernel<<<1024, 256>>>(x);
    attn_kernel<<<1, 128>>>(logdet, off1, off2, off3, out, out_size);
    out_kernel<<<12288, 256>>>(x, out);
}

// round 9
// speedup vs baseline: 1.1304x; 1.1304x over previous
#include <cuda_runtime.h>
#include <math.h>

#define Bn 128
#define Cn 48
#define Hn 64
#define Wn 64
#define Pn 32
#define OUT_ELEMS (Bn*Cn*Hn*Wn)

// Scratch (no allocations allowed)
__device__ unsigned long long g_M2[Cn*Cn];   // M duplicated (m,m) as f32x2
__device__ float4 g_Spart[1024];             // partials: idx = (b*2+g)*4 + kq
__device__ float  g_A[Bn*2*4];               // attn coeffs per (b,g)

#define FMA2(acc, mm, vv) asm("fma.rn.f32x2 %0, %1, %2, %0;" : "+l"(acc) : "l"(mm), "l"(vv))
#define PACK2(dst, lo, hi) asm("mov.b64 %0, {%1,%2};" : "=l"(dst) : "f"(lo), "f"(hi))
#define UNPACK2(lo, hi, src) asm("mov.b64 {%0,%1}, %2;" : "=f"(lo), "=f"(hi) : "l"(src))

// ---------------------------------------------------------------------------
// Kernel A: prep. 9 blocks x 256 threads, smem-staged W, 1 output/thread.
// ---------------------------------------------------------------------------
__global__ __launch_bounds__(256) void prep_kernel(
        const float* __restrict__ Wq1, const float* __restrict__ Wq2,
        const float* __restrict__ Wq3, const float* __restrict__ Wk1,
        const float* __restrict__ Wk2, const float* __restrict__ Wk3) {
    __shared__ float sW[6][Cn*Cn];   // 55296 B

    const int tid = threadIdx.x;
    const float* Ws[6] = {Wq1, Wk1, Wq2, Wk2, Wq3, Wk3};
    #pragma unroll
    for (int m = 0; m < 6; ++m)
        for (int i = tid; i < Cn*Cn; i += 256) sW[m][i] = Ws[m][i];
    __syncthreads();

    int w = blockIdx.x * 256 + tid;          // 0..2303
    int c = w / Cn, c2 = w % Cn;
    float s = 0.f;
    #pragma unroll
    for (int o = 0; o < Cn; ++o) {
        s += sW[0][o*Cn+c]*sW[1][o*Cn+c2]
           + sW[2][o*Cn+c]*sW[3][o*Cn+c2]
           + sW[4][o*Cn+c]*sW[5][o*Cn+c2];
    }
    s *= (1.0f / sqrtf((float)(Cn*Pn*Pn)));
    ((float2*)g_M2)[w] = make_float2(s, s);
}

// ---------------------------------------------------------------------------
// Kernel B: scores — EXACT R6 form (measured-good). Grid 1024:
// bid -> (b, g, k-quarter kq). Block 256 = 8 warps.
// ---------------------------------------------------------------------------
__global__ __launch_bounds__(256, 3) void score_kernel(const float* __restrict__ x) {
    __shared__ unsigned long long sV[Cn*128];   // 49152 B  [c][k]
    __shared__ unsigned long long sM2[Cn*Cn];   // 18432 B
    __shared__ float4 sred[8];

    const int bid = blockIdx.x;
    const int kq = bid & 3;            // k-quarter (8 y-rows)
    const int g  = (bid >> 2) & 1;     // column-parity group
    const int b  = bid >> 3;
    const int tid = threadIdx.x;

    for (int i = tid; i < Cn*Cn; i += 256) sM2[i] = g_M2[i];

    const float2* xb2 = (const float2*)(x + (size_t)b * Cn * Hn * Wn);

    for (int idx = tid; idx < Cn*128; idx += 256) {
        int c2 = idx >> 7;
        int k  = idx & 127;
        int yy = k >> 4;
        int xx = k & 15;
        int yt = kq*8 + yy;
        float2 a  = xb2[((size_t)c2*Hn + yt)*32      + g*16 + xx];
        float2 bb = xb2[((size_t)c2*Hn + yt + 32)*32 + g*16 + xx];
        unsigned long long pk;
        if (g == 0) PACK2(pk, a.x, bb.x);
        else        PACK2(pk, a.y, bb.y);
        sV[idx] = pk;
    }
    __syncthreads();

    const int ci = tid >> 5;           // warp id: M-row group
    const int kl = tid & 31;           // k lane

    unsigned long long acc[24];
    #pragma unroll
    for (int i = 0; i < 24; ++i) acc[i] = 0ULL;

    #pragma unroll
    for (int c2 = 0; c2 < Cn; ++c2) {
        unsigned long long v0 = sV[c2*128 + kl];
        unsigned long long v1 = sV[c2*128 + kl + 32];
        unsigned long long v2 = sV[c2*128 + kl + 64];
        unsigned long long v3 = sV[c2*128 + kl + 96];
        #pragma unroll
        for (int r = 0; r < 6; ++r) {
            unsigned long long m = sM2[(ci*6 + r)*Cn + c2];   // broadcast
            FMA2(acc[r*4    ], m, v0);
            FMA2(acc[r*4 + 1], m, v1);
            FMA2(acc[r*4 + 2], m, v2);
            FMA2(acc[r*4 + 3], m, v3);
        }
    }

    float p00 = 0.f, p01 = 0.f, p10 = 0.f, p11 = 0.f;
    #pragma unroll
    for (int r = 0; r < 6; ++r) {
        #pragma unroll
        for (int j = 0; j < 4; ++j) {
            float wt, wb, vt, vb;
            UNPACK2(wt, wb, acc[r*4 + j]);
            unsigned long long v = sV[(ci*6 + r)*128 + kl + j*32];
            UNPACK2(vt, vb, v);
            p00 = fmaf(vt, wt, p00);  p01 = fmaf(vt, wb, p01);
            p10 = fmaf(vb, wt, p10);  p11 = fmaf(vb, wb, p11);
        }
    }

    #pragma unroll
    for (int off = 16; off; off >>= 1) {
        p00 += __shfl_xor_sync(0xffffffffu, p00, off);
        p01 += __shfl_xor_sync(0xffffffffu, p01, off);
        p10 += __shfl_xor_sync(0xffffffffu, p10, off);
        p11 += __shfl_xor_sync(0xffffffffu, p11, off);
    }
    if (kl == 0) sred[ci] = make_float4(p00, p01, p10, p11);
    __syncthreads();
    if (tid == 0) {
        float4 sv = sred[0];
        #pragma unroll
        for (int w = 1; w < 8; ++w) {
            float4 t = sred[w];
            sv.x += t.x; sv.y += t.y; sv.z += t.z; sv.w += t.w;
        }
        g_Spart[(b*2+g)*4 + kq] = sv;
    }
}

// ---------------------------------------------------------------------------
// Kernel C: softmax coeffs + logdet.
// ---------------------------------------------------------------------------
__global__ void attn_kernel(const float* __restrict__ logdet_in,
                            const float* __restrict__ off1p,
                            const float* __restrict__ off2p,
                            const float* __restrict__ off3p,
                            float* __restrict__ out, int out_size) {
    int b = threadIdx.x;
    if (b >= Bn) return;
    const float off  = off1p[0];
    const float off2 = off2p[0];
    const float off3 = off3p[0];
    float ld = logdet_in[b];

    #pragma unroll
    for (int g = 0; g < 2; ++g) {
        float4 s = g_Spart[(b*2+g)*4 + 0];
        #pragma unroll
        for (int qq = 1; qq < 4; ++qq) {
            float4 t = g_Spart[(b*2+g)*4 + qq];
            s.x += t.x; s.y += t.y; s.z += t.z; s.w += t.w;
        }
        float stt = s.x + off3, stb = s.y + off3;
        float sbt = s.z + off3, sbb = s.w + off3;
        float z = off3;

        float mx   = fmaxf(fmaxf(stt, stb), z);
        float e0   = expf(stt-mx), e1 = expf(stb-mx), ez = expf(z-mx);
        float inv  = 1.f / (e0 + e1 + 2.f*ez);
        float a_tt = e0*inv + off2 + off;
        float a_tb = e1*inv + off2;

        mx  = fmaxf(fmaxf(sbt, sbb), z);
        e0  = expf(sbt-mx); e1 = expf(sbb-mx); ez = expf(z-mx);
        inv = 1.f / (e0 + e1 + 2.f*ez);
        float a_bt = e0*inv + off2;
        float a_bb = e1*inv + off2 + off;

        float det = a_tt*a_bb - a_tb*a_bt;
        ld += logf(fabsf(det)) * (float)(Pn*(Pn/2)*Cn);

        float* a = &g_A[(b*2+g)*4];
        a[0]=a_tt; a[1]=a_tb; a[2]=a_bt; a[3]=a_bb;
    }
    if (OUT_ELEMS + b < out_size) out[OUT_ELEMS + b] = ld;
}

// ---------------------------------------------------------------------------
// Kernel D: output assembly. __stwt stores + REVERSED batch order: out
// consumes x in score's reverse-finish order so first-touched lines are the
// LRU-hottest in L2 (score walked b ascending; we walk b descending).
// ---------------------------------------------------------------------------
__global__ __launch_bounds__(256) void out_kernel(const float* __restrict__ x,
                                                  float* __restrict__ out) {
    int t  = blockIdx.x * blockDim.x + threadIdx.x;
    int x4 = t & 15;
    int y  = (t >> 4) & 31;
    int r  = t >> 9;
    int c  = r % Cn;
    int b  = Bn - 1 - (r / Cn);        // reversed batch order
    int g  = x4 >> 3;

    const float* A = &g_A[(b*2+g)*4];
    float a_tt = __ldg(&A[0]), a_tb = __ldg(&A[1]);
    float a_bt = __ldg(&A[2]), a_bb = __ldg(&A[3]);

    size_t base = (((size_t)b*Cn + c)*Hn + y)*Wn + x4*4;
    float4 xt = *(const float4*)(x + base);
    float4 xb = *(const float4*)(x + base + 32*Wn);
    float4 ot, ob;
    if (g == 0) {  // pass-through at even lane (x,z)
        ot.x = xt.x;                    ob.x = xb.x;
        ot.y = a_tt*xt.y + a_tb*xb.y;   ob.y = a_bt*xt.y + a_bb*xb.y;
        ot.z = xt.z;                    ob.z = xb.z;
        ot.w = a_tt*xt.w + a_tb*xb.w;   ob.w = a_bt*xt.w + a_bb*xb.w;
    } else {       // pass-through at odd lane (y,w)
        ot.x = a_tt*xt.x + a_tb*xb.x;   ob.x = a_bt*xt.x + a_bb*xb.x;
        ot.y = xt.y;                    ob.y = xb.y;
        ot.z = a_tt*xt.z + a_tb*xb.z;   ob.z = a_bt*xt.z + a_bb*xb.z;
        ot.w = xt.w;                    ob.w = xb.w;
    }
    __stwt((float4*)(out + base), ot);
    __stwt((float4*)(out + base + 32*Wn), ob);
}

// ---------------------------------------------------------------------------
extern "C" void kernel_launch(void* const* d_in, const int* in_sizes, int n_in,
                              void* d_out, int out_size) {
    const float* x      = (const float*)d_in[0];
    const float* logdet = (const float*)d_in[1];
    const float* Wq1    = (const float*)d_in[2];
    const float* Wq2    = (const float*)d_in[3];
    const float* Wq3    = (const float*)d_in[4];
    const float* Wk1    = (const float*)d_in[5];
    const float* Wk2    = (const float*)d_in[6];
    const float* Wk3    = (const float*)d_in[7];
    const float* off1   = (const float*)d_in[8];
    const float* off2   = (const float*)d_in[9];
    const float* off3   = (const float*)d_in[10];
    float* out = (float*)d_out;

    prep_kernel<<<9, 256>>>(Wq1, Wq2, Wq3, Wk1, Wk2, Wk3);
    score_kernel<<<1024, 256>>>(x);
    attn_kernel<<<1, 128>>>(logdet, off1, off2, off3, out, out_size);
    out_kernel<<<12288, 256>>>(x, out);
}